// round 1
// baseline (speedup 1.0000x reference)
#include <cuda_runtime.h>

#define HIDDEN 32
#define FEAT 30
#define TSTEPS 512
#define BATCH 4096
#define WARPS_PER_BLOCK 8
#define FULLMASK 0xffffffffu

__device__ __forceinline__ float sigf(float x) {
    float e = __expf(-x);
    return __fdividef(1.0f, 1.0f + e);
}
__device__ __forceinline__ float tanh_fast(float x) {
    float e = __expf(-2.0f * x);
    return __fdividef(1.0f - e, 1.0f + e);
}

__global__ void __launch_bounds__(WARPS_PER_BLOCK * 32)
lstm_fused_kernel(
    const float* __restrict__ x, const float* __restrict__ h0, const float* __restrict__ c0,
    const float* __restrict__ W_ih, const float* __restrict__ W_hh,
    const float* __restrict__ b_ih, const float* __restrict__ b_hh,
    const float* __restrict__ W_all, const float* __restrict__ b_all,
    const float* __restrict__ W_pos, const float* __restrict__ b_pos,
    const float* __restrict__ W_lv, const float* __restrict__ b_lv,
    float* __restrict__ out)
{
    // Weights transposed + gate-packed for LDS.128 per k:
    //   sWih[k][j] = (W_ih[i-gate,j][k], W_ih[f][k], W_ih[g][k], W_ih[o][k])
    __shared__ float4 sWih[FEAT][HIDDEN];
    __shared__ float4 sWhh[HIDDEN][HIDDEN];
    __shared__ float  sWallT[HIDDEN][HIDDEN];  // [k][j] = W_all[j][k]

    const int tid = threadIdx.x;
    for (int idx = tid; idx < FEAT * HIDDEN; idx += blockDim.x) {
        int k = idx / HIDDEN, j = idx % HIDDEN;
        sWih[k][j] = make_float4(W_ih[(j) * FEAT + k],
                                 W_ih[(32 + j) * FEAT + k],
                                 W_ih[(64 + j) * FEAT + k],
                                 W_ih[(96 + j) * FEAT + k]);
    }
    for (int idx = tid; idx < HIDDEN * HIDDEN; idx += blockDim.x) {
        int k = idx / HIDDEN, j = idx % HIDDEN;
        sWhh[k][j] = make_float4(W_hh[(j) * HIDDEN + k],
                                 W_hh[(32 + j) * HIDDEN + k],
                                 W_hh[(64 + j) * HIDDEN + k],
                                 W_hh[(96 + j) * HIDDEN + k]);
        sWallT[k][j] = W_all[j * HIDDEN + k];
    }
    __syncthreads();

    const int warp = tid >> 5;
    const int lane = tid & 31;
    const int b = blockIdx.x * WARPS_PER_BLOCK + warp;   // grid sized exactly: 4096 warps

    const float* xb = x + (size_t)b * (TSTEPS * FEAT);

    float h = h0[b * HIDDEN + lane];
    float c = c0[b * HIDDEN + lane];
    const float bi = b_ih[lane]      + b_hh[lane];
    const float bf = b_ih[32 + lane] + b_hh[32 + lane];
    const float bg = b_ih[64 + lane] + b_hh[64 + lane];
    const float bo = b_ih[96 + lane] + b_hh[96 + lane];
    const float ball = b_all[lane];
    const float wp0 = W_pos[lane], wp1 = W_pos[32 + lane], wlv = W_lv[lane];
    const float bp0 = b_pos[0], bp1 = b_pos[1], blv = b_lv[0];

    // Masked-step outputs are constants: fc = b_all -> pos const; lv = sigmoid(b_lv).
    float cp0 = ball * wp0, cp1 = ball * wp1;
    #pragma unroll
    for (int s = 16; s; s >>= 1) {
        cp0 += __shfl_xor_sync(FULLMASK, cp0, s);
        cp1 += __shfl_xor_sync(FULLMASK, cp1, s);
    }
    cp0 += bp0; cp1 += bp1;
    const float clv = sigf(blv);

    float* pos_out = out;                                        // [B,T,2]
    float* lv_out  = out + (size_t)BATCH * TSTEPS * 2;           // [B,T,1]
    float* hT_out  = out + (size_t)BATCH * TSTEPS * 3;           // [1,B,H]
    float* cT_out  = hT_out + BATCH * HIDDEN;                    // [1,B,H]

    float xv = (lane < FEAT) ? xb[lane] : 0.0f;   // x_t staged in lane registers

    for (int t = 0; t < TSTEPS; ++t) {
        // Prefetch next timestep's features while computing this one.
        float xn = 0.0f;
        if (t + 1 < TSTEPS && lane < FEAT) xn = xb[(size_t)(t + 1) * FEAT + lane];

        const float bitv = __shfl_sync(FULLMASK, xv, FEAT - 1);
        const size_t ot = (size_t)b * TSTEPS + t;

        if (bitv == 1.0f) {
            float ai = bi, af = bf, ag = bg, ao = bo;
            #pragma unroll
            for (int k = 0; k < FEAT; ++k) {
                float v = __shfl_sync(FULLMASK, xv, k);
                float4 w = sWih[k][lane];
                ai = fmaf(v, w.x, ai); af = fmaf(v, w.y, af);
                ag = fmaf(v, w.z, ag); ao = fmaf(v, w.w, ao);
            }
            #pragma unroll
            for (int k = 0; k < HIDDEN; ++k) {
                float v = __shfl_sync(FULLMASK, h, k);
                float4 w = sWhh[k][lane];
                ai = fmaf(v, w.x, ai); af = fmaf(v, w.y, af);
                ag = fmaf(v, w.z, ag); ao = fmaf(v, w.w, ao);
            }
            const float ig = sigf(ai);
            const float fg = sigf(af);
            const float gg = tanh_fast(ag);
            const float og = sigf(ao);
            c = fmaf(fg, c, ig * gg);
            h = og * tanh_fast(c);

            // Fused heads: fc = h @ W_all^T + b_all ; pos = fc @ W_pos^T + b_pos ; lv = sig(h @ W_lv^T)
            float fc = ball;
            #pragma unroll
            for (int k = 0; k < HIDDEN; ++k) {
                float v = __shfl_sync(FULLMASK, h, k);
                fc = fmaf(v, sWallT[k][lane], fc);
            }
            float p0 = fc * wp0, p1 = fc * wp1, pl = h * wlv;
            #pragma unroll
            for (int s = 16; s; s >>= 1) {
                p0 += __shfl_xor_sync(FULLMASK, p0, s);
                p1 += __shfl_xor_sync(FULLMASK, p1, s);
                pl += __shfl_xor_sync(FULLMASK, pl, s);
            }
            if (lane == 0) {
                *reinterpret_cast<float2*>(pos_out + ot * 2) =
                    make_float2(p0 + bp0, p1 + bp1);
                lv_out[ot] = sigf(pl + blv);
            }
        } else {
            // mask==0: h,c unchanged; hs row is zeros -> constant head outputs
            if (lane == 0) {
                *reinterpret_cast<float2*>(pos_out + ot * 2) = make_float2(cp0, cp1);
                lv_out[ot] = clv;
            }
        }
        xv = xn;
    }

    hT_out[b * HIDDEN + lane] = h;
    cT_out[b * HIDDEN + lane] = c;
}

extern "C" void kernel_launch(void* const* d_in, const int* in_sizes, int n_in,
                              void* d_out, int out_size)
{
    const float* x    = (const float*)d_in[0];
    const float* h0   = (const float*)d_in[1];
    const float* c0   = (const float*)d_in[2];
    const float* W_ih = (const float*)d_in[3];
    const float* W_hh = (const float*)d_in[4];
    const float* b_ih = (const float*)d_in[5];
    const float* b_hh = (const float*)d_in[6];
    const float* W_all= (const float*)d_in[7];
    const float* b_all= (const float*)d_in[8];
    const float* W_pos= (const float*)d_in[9];
    const float* b_pos= (const float*)d_in[10];
    const float* W_lv = (const float*)d_in[11];
    const float* b_lv = (const float*)d_in[12];
    float* out = (float*)d_out;

    dim3 grid(BATCH / WARPS_PER_BLOCK);      // 512 blocks
    dim3 block(WARPS_PER_BLOCK * 32);        // 256 threads = 8 samples/block
    lstm_fused_kernel<<<grid, block>>>(x, h0, c0, W_ih, W_hh, b_ih, b_hh,
                                       W_all, b_all, W_pos, b_pos, W_lv, b_lv, out);
}

// round 2
// speedup vs baseline: 1.4992x; 1.4992x over previous
#include <cuda_runtime.h>

#define HIDDEN 32
#define FEAT 30
#define TSTEPS 512
#define BATCH 4096
#define WARPS_PER_BLOCK 8
#define FULLMASK 0xffffffffu

typedef unsigned long long ull;

__device__ __forceinline__ float sigf(float x) {
    float e = __expf(-x);
    return __fdividef(1.0f, 1.0f + e);
}
__device__ __forceinline__ float tanh_fast(float x) {
    float e = __expf(-2.0f * x);
    return __fdividef(1.0f - e, 1.0f + e);
}

// Blackwell packed fp32x2 ops (ptxas never auto-fuses these)
__device__ __forceinline__ ull fma2(ull a, ull b, ull c) {
    ull d;
    asm("fma.rn.f32x2 %0, %1, %2, %3;" : "=l"(d) : "l"(a), "l"(b), "l"(c));
    return d;
}
__device__ __forceinline__ ull add2(ull a, ull b) {
    ull d;
    asm("add.rn.f32x2 %0, %1, %2;" : "=l"(d) : "l"(a), "l"(b));
    return d;
}
__device__ __forceinline__ ull pack2(float lo, float hi) {
    ull d; asm("mov.b64 %0, {%1, %2};" : "=l"(d) : "f"(lo), "f"(hi)); return d;
}
__device__ __forceinline__ float2 unpack2(ull v) {
    float lo, hi; asm("mov.b64 {%0, %1}, %2;" : "=f"(lo), "=f"(hi) : "l"(v));
    return make_float2(lo, hi);
}

__global__ void __launch_bounds__(WARPS_PER_BLOCK * 32, 1)
lstm_fused_kernel(
    const float* __restrict__ x, const float* __restrict__ h0, const float* __restrict__ c0,
    const float* __restrict__ W_ih, const float* __restrict__ W_hh,
    const float* __restrict__ b_ih, const float* __restrict__ b_hh,
    const float* __restrict__ W_all, const float* __restrict__ b_all,
    const float* __restrict__ W_pos, const float* __restrict__ b_pos,
    const float* __restrict__ W_lv, const float* __restrict__ b_lv,
    float* __restrict__ out)
{
    // W_ih transposed + gate-packed as f32x2 pairs: [k][j] = ((w_i,w_f),(w_g,w_o))
    __shared__ ulonglong2 sWih[FEAT][HIDDEN];

    const int tid = threadIdx.x;
    for (int idx = tid; idx < FEAT * HIDDEN; idx += blockDim.x) {
        int k = idx / HIDDEN, j = idx % HIDDEN;
        ulonglong2 w;
        w.x = pack2(W_ih[j * FEAT + k],        W_ih[(32 + j) * FEAT + k]);
        w.y = pack2(W_ih[(64 + j) * FEAT + k], W_ih[(96 + j) * FEAT + k]);
        sWih[k][j] = w;
    }
    __syncthreads();

    const int warp = tid >> 5;
    const int lane = tid & 31;
    const int b = blockIdx.x * WARPS_PER_BLOCK + warp;   // 4096 warps exactly

    const float* xb = x + (size_t)b * (TSTEPS * FEAT);

    float h = h0[b * HIDDEN + lane];
    float c = c0[b * HIDDEN + lane];

    // Gate biases packed (i,f) / (g,o)
    const ull bias_if = pack2(b_ih[lane]      + b_hh[lane],
                              b_ih[32 + lane] + b_hh[32 + lane]);
    const ull bias_go = pack2(b_ih[64 + lane] + b_hh[64 + lane],
                              b_ih[96 + lane] + b_hh[96 + lane]);

    // W_hh register-resident, gate-packed: loop-invariant across all 512 steps.
    ull whh_if[HIDDEN], whh_go[HIDDEN];
    #pragma unroll
    for (int k = 0; k < HIDDEN; ++k) {
        whh_if[k] = pack2(W_hh[lane * HIDDEN + k],        W_hh[(32 + lane) * HIDDEN + k]);
        whh_go[k] = pack2(W_hh[(64 + lane) * HIDDEN + k], W_hh[(96 + lane) * HIDDEN + k]);
    }

    // Folded heads: pos = h @ Wc^T + cb,  Wc = W_pos @ W_all (2x32),
    // cb = W_pos @ b_all + b_pos. lv = sigmoid(h @ W_lv^T + b_lv).
    float wc0 = 0.0f, wc1 = 0.0f, cb0 = b_pos[0], cb1 = b_pos[1];
    #pragma unroll
    for (int k = 0; k < HIDDEN; ++k) {
        float wa = W_all[k * HIDDEN + lane];
        wc0 = fmaf(W_pos[k],      wa, wc0);
        wc1 = fmaf(W_pos[32 + k], wa, wc1);
        cb0 = fmaf(W_pos[k],      b_all[k], cb0);
        cb1 = fmaf(W_pos[32 + k], b_all[k], cb1);
    }
    const float wlv = W_lv[lane];
    const float blv = b_lv[0];
    const float clv = sigf(blv);          // masked-step lv constant

    float* pos_out = out;                                   // [B,T,2]
    float* lv_out  = out + (size_t)BATCH * TSTEPS * 2;      // [B,T,1]
    float* hT_out  = out + (size_t)BATCH * TSTEPS * 3;      // [1,B,H]
    float* cT_out  = hT_out + BATCH * HIDDEN;               // [1,B,H]

    float xv = (lane < FEAT) ? xb[lane] : 0.0f;

    for (int t = 0; t < TSTEPS; ++t) {
        float xn = 0.0f;
        if (t + 1 < TSTEPS && lane < FEAT) xn = xb[(size_t)(t + 1) * FEAT + lane];

        const float bitv = __shfl_sync(FULLMASK, xv, FEAT - 1);
        const size_t ot = (size_t)b * TSTEPS + t;

        if (bitv == 1.0f) {
            // Two accumulator chains per gate-pair to break the FMA RAW chain.
            ull aif0 = bias_if, ago0 = bias_go;
            ull aif1 = 0ULL,    ago1 = 0ULL;     // (0.0f, 0.0f)

            #pragma unroll
            for (int k = 0; k < FEAT; k += 2) {
                float v0 = __shfl_sync(FULLMASK, xv, k);
                ull vv0 = pack2(v0, v0);
                ulonglong2 w0 = sWih[k][lane];
                aif0 = fma2(vv0, w0.x, aif0);
                ago0 = fma2(vv0, w0.y, ago0);
                float v1 = __shfl_sync(FULLMASK, xv, k + 1);
                ull vv1 = pack2(v1, v1);
                ulonglong2 w1 = sWih[k + 1][lane];
                aif1 = fma2(vv1, w1.x, aif1);
                ago1 = fma2(vv1, w1.y, ago1);
            }
            #pragma unroll
            for (int k = 0; k < HIDDEN; k += 2) {
                float v0 = __shfl_sync(FULLMASK, h, k);
                ull vv0 = pack2(v0, v0);
                aif0 = fma2(vv0, whh_if[k], aif0);
                ago0 = fma2(vv0, whh_go[k], ago0);
                float v1 = __shfl_sync(FULLMASK, h, k + 1);
                ull vv1 = pack2(v1, v1);
                aif1 = fma2(vv1, whh_if[k + 1], aif1);
                ago1 = fma2(vv1, whh_go[k + 1], ago1);
            }
            float2 aif = unpack2(add2(aif0, aif1));
            float2 ago = unpack2(add2(ago0, ago1));

            const float ig = sigf(aif.x);
            const float fg = sigf(aif.y);
            const float gg = tanh_fast(ago.x);
            const float og = sigf(ago.y);
            c = fmaf(fg, c, ig * gg);
            h = og * tanh_fast(c);

            // Folded heads: 3 per-lane products + one 3-value butterfly.
            float p0 = h * wc0, p1 = h * wc1, pl = h * wlv;
            #pragma unroll
            for (int s = 16; s; s >>= 1) {
                p0 += __shfl_xor_sync(FULLMASK, p0, s);
                p1 += __shfl_xor_sync(FULLMASK, p1, s);
                pl += __shfl_xor_sync(FULLMASK, pl, s);
            }
            if (lane == 0) {
                *reinterpret_cast<float2*>(pos_out + ot * 2) =
                    make_float2(p0 + cb0, p1 + cb1);
                lv_out[ot] = sigf(pl + blv);
            }
        } else {
            // mask==0: h,c carried; hs row = 0 -> constant head outputs.
            if (lane == 0) {
                *reinterpret_cast<float2*>(pos_out + ot * 2) = make_float2(cb0, cb1);
                lv_out[ot] = clv;
            }
        }
        xv = xn;
    }

    hT_out[b * HIDDEN + lane] = h;
    cT_out[b * HIDDEN + lane] = c;
}

extern "C" void kernel_launch(void* const* d_in, const int* in_sizes, int n_in,
                              void* d_out, int out_size)
{
    const float* x    = (const float*)d_in[0];
    const float* h0   = (const float*)d_in[1];
    const float* c0   = (const float*)d_in[2];
    const float* W_ih = (const float*)d_in[3];
    const float* W_hh = (const float*)d_in[4];
    const float* b_ih = (const float*)d_in[5];
    const float* b_hh = (const float*)d_in[6];
    const float* W_all= (const float*)d_in[7];
    const float* b_all= (const float*)d_in[8];
    const float* W_pos= (const float*)d_in[9];
    const float* b_pos= (const float*)d_in[10];
    const float* W_lv = (const float*)d_in[11];
    const float* b_lv = (const float*)d_in[12];
    float* out = (float*)d_out;

    dim3 grid(BATCH / WARPS_PER_BLOCK);      // 512 blocks
    dim3 block(WARPS_PER_BLOCK * 32);        // 256 threads
    lstm_fused_kernel<<<grid, block>>>(x, h0, c0, W_ih, W_hh, b_ih, b_hh,
                                       W_all, b_all, W_pos, b_pos, W_lv, b_lv, out);
}

// round 3
// speedup vs baseline: 2.6407x; 1.7614x over previous
#include <cuda_runtime.h>

#define HIDDEN 32
#define FEAT 30
#define TSTEPS 512
#define BATCH 4096
#define CHUNK 16
#define FULLMASK 0xffffffffu

typedef unsigned long long ull;

__device__ __forceinline__ float sigf(float x) {
    float e = __expf(-x);
    return __fdividef(1.0f, 1.0f + e);
}
__device__ __forceinline__ float tanh_fast(float x) {
    float e = __expf(-2.0f * x);
    return __fdividef(1.0f - e, 1.0f + e);
}
__device__ __forceinline__ ull fma2(ull a, ull b, ull c) {
    ull d;
    asm("fma.rn.f32x2 %0, %1, %2, %3;" : "=l"(d) : "l"(a), "l"(b), "l"(c));
    return d;
}
__device__ __forceinline__ ull pack2(float lo, float hi) {
    ull d; asm("mov.b64 %0, {%1, %2};" : "=l"(d) : "f"(lo), "f"(hi)); return d;
}
__device__ __forceinline__ ull dup2(float v) {
    ull d; asm("mov.b64 %0, {%1, %1};" : "=l"(d) : "f"(v)); return d;
}
__device__ __forceinline__ float2 unpack2(ull v) {
    float lo, hi; asm("mov.b64 {%0, %1}, %2;" : "=f"(lo), "=f"(hi) : "l"(v));
    return make_float2(lo, hi);
}

__global__ void __launch_bounds__(32)
lstm_fused_kernel(
    const float* __restrict__ x, const float* __restrict__ h0, const float* __restrict__ c0,
    const float* __restrict__ W_ih, const float* __restrict__ W_hh,
    const float* __restrict__ b_ih, const float* __restrict__ b_hh,
    const float* __restrict__ W_all, const float* __restrict__ b_all,
    const float* __restrict__ W_pos, const float* __restrict__ b_pos,
    const float* __restrict__ W_lv, const float* __restrict__ b_lv,
    float* __restrict__ out)
{
    // sWih[k][j] = ((w_i,w_f),(w_g,w_o)) gate-packed f32x2 pairs (shared by 4 samples)
    __shared__ ulonglong2 sWih[FEAT][HIDDEN];
    __shared__ ull hbuf[2][2][HIDDEN];        // [buf][pairAB/CD][j] packed carried h
    __shared__ ull xbuf[2][2][HIDDEN];        // [buf][pair][k]  packed x_t (k<30)
    __shared__ ull hist[CHUNK * 2 * 33];      // [(t*2+pair)*33 + j] masked h, padded
    __shared__ ull wcd0[HIDDEN], wcd1[HIDDEN], wcdl[HIDDEN];  // dup'd head weights

    const int lane = threadIdx.x;
    const int s0 = blockIdx.x * 4;            // 4 samples per warp/block

    // ---- one-time init ----
    #pragma unroll
    for (int k = 0; k < FEAT; ++k) {
        ulonglong2 w;
        w.x = pack2(W_ih[lane * FEAT + k],        W_ih[(32 + lane) * FEAT + k]);
        w.y = pack2(W_ih[(64 + lane) * FEAT + k], W_ih[(96 + lane) * FEAT + k]);
        sWih[k][lane] = w;
    }
    ull whh_if[HIDDEN], whh_go[HIDDEN];       // register-resident, shared by 4 samples
    #pragma unroll
    for (int k = 0; k < HIDDEN; ++k) {
        whh_if[k] = pack2(W_hh[lane * HIDDEN + k],        W_hh[(32 + lane) * HIDDEN + k]);
        whh_go[k] = pack2(W_hh[(64 + lane) * HIDDEN + k], W_hh[(96 + lane) * HIDDEN + k]);
    }
    // folded heads: wc = W_pos @ W_all, cb = W_pos @ b_all + b_pos
    float wc0 = 0.f, wc1 = 0.f, cb0 = b_pos[0], cb1 = b_pos[1];
    #pragma unroll
    for (int m = 0; m < HIDDEN; ++m) {
        float wa = W_all[m * HIDDEN + lane];
        wc0 = fmaf(W_pos[m],      wa, wc0);
        wc1 = fmaf(W_pos[32 + m], wa, wc1);
        cb0 = fmaf(W_pos[m],      b_all[m], cb0);
        cb1 = fmaf(W_pos[32 + m], b_all[m], cb1);
    }
    wcd0[lane] = dup2(wc0);
    wcd1[lane] = dup2(wc1);
    wcdl[lane] = dup2(W_lv[lane]);
    const float blv = b_lv[0];

    const ull bias_if = pack2(b_ih[lane]      + b_hh[lane],
                              b_ih[32 + lane] + b_hh[32 + lane]);
    const ull bias_go = pack2(b_ih[64 + lane] + b_hh[64 + lane],
                              b_ih[96 + lane] + b_hh[96 + lane]);

    const float* xA = x + (size_t)(s0 + 0) * TSTEPS * FEAT;
    const float* xB = x + (size_t)(s0 + 1) * TSTEPS * FEAT;
    const float* xC = x + (size_t)(s0 + 2) * TSTEPS * FEAT;
    const float* xD = x + (size_t)(s0 + 3) * TSTEPS * FEAT;

    float hA = h0[(s0 + 0) * HIDDEN + lane], cA = c0[(s0 + 0) * HIDDEN + lane];
    float hB = h0[(s0 + 1) * HIDDEN + lane], cB = c0[(s0 + 1) * HIDDEN + lane];
    float hC = h0[(s0 + 2) * HIDDEN + lane], cC = c0[(s0 + 2) * HIDDEN + lane];
    float hD = h0[(s0 + 3) * HIDDEN + lane], cD = c0[(s0 + 3) * HIDDEN + lane];

    hbuf[0][0][lane] = pack2(hA, hB);
    hbuf[0][1][lane] = pack2(hC, hD);
    if (lane < FEAT) {
        xbuf[0][0][lane] = pack2(xA[lane], xB[lane]);
        xbuf[0][1][lane] = pack2(xC[lane], xD[lane]);
    }
    __syncwarp();

    float* pos_out = out;                                   // [B,T,2]
    float* lv_out  = out + (size_t)BATCH * TSTEPS * 2;      // [B,T,1]
    float* hT_out  = out + (size_t)BATCH * TSTEPS * 3;      // [1,B,H]
    float* cT_out  = hT_out + BATCH * HIDDEN;               // [1,B,H]

    for (int t = 0; t < TSTEPS; ++t) {
        const int bsel = t & 1;
        const int slot = t & (CHUNK - 1);

        // prefetch next x
        float xnA = 0.f, xnB = 0.f, xnC = 0.f, xnD = 0.f;
        const bool pf = (t + 1 < TSTEPS) && (lane < FEAT);
        if (pf) {
            const int o = (t + 1) * FEAT + lane;
            xnA = xA[o]; xnB = xB[o]; xnC = xC[o]; xnD = xD[o];
        }

        const float2 mAB = unpack2(xbuf[bsel][0][FEAT - 1]);
        const float2 mCD = unpack2(xbuf[bsel][1][FEAT - 1]);
        const bool aA = (mAB.x == 1.0f), aB = (mAB.y == 1.0f);
        const bool aC = (mCD.x == 1.0f), aD = (mCD.y == 1.0f);

        if (aA | aB | aC | aD) {
            ull ifA = bias_if, goA = bias_go, ifB = bias_if, goB = bias_go;
            ull ifC = bias_if, goC = bias_go, ifD = bias_if, goD = bias_go;
            #pragma unroll
            for (int k = 0; k < FEAT; ++k) {
                const float2 uab = unpack2(xbuf[bsel][0][k]);
                const float2 ucd = unpack2(xbuf[bsel][1][k]);
                const ulonglong2 w = sWih[k][lane];
                const ull vA = dup2(uab.x), vB = dup2(uab.y);
                const ull vC = dup2(ucd.x), vD = dup2(ucd.y);
                ifA = fma2(vA, w.x, ifA); goA = fma2(vA, w.y, goA);
                ifB = fma2(vB, w.x, ifB); goB = fma2(vB, w.y, goB);
                ifC = fma2(vC, w.x, ifC); goC = fma2(vC, w.y, goC);
                ifD = fma2(vD, w.x, ifD); goD = fma2(vD, w.y, goD);
            }
            #pragma unroll
            for (int k = 0; k < HIDDEN; ++k) {
                const float2 uab = unpack2(hbuf[bsel][0][k]);
                const float2 ucd = unpack2(hbuf[bsel][1][k]);
                const ull wi = whh_if[k], wg = whh_go[k];
                const ull vA = dup2(uab.x), vB = dup2(uab.y);
                const ull vC = dup2(ucd.x), vD = dup2(ucd.y);
                ifA = fma2(vA, wi, ifA); goA = fma2(vA, wg, goA);
                ifB = fma2(vB, wi, ifB); goB = fma2(vB, wg, goB);
                ifC = fma2(vC, wi, ifC); goC = fma2(vC, wg, goC);
                ifD = fma2(vD, wi, ifD); goD = fma2(vD, wg, goD);
            }
            float hsA, hsB, hsC, hsD;
            {
                float2 g1 = unpack2(ifA), g2 = unpack2(goA);
                float cn = fmaf(sigf(g1.y), cA, sigf(g1.x) * tanh_fast(g2.x));
                float hn = sigf(g2.y) * tanh_fast(cn);
                cA = aA ? cn : cA; hA = aA ? hn : hA; hsA = aA ? hn : 0.f;
            }
            {
                float2 g1 = unpack2(ifB), g2 = unpack2(goB);
                float cn = fmaf(sigf(g1.y), cB, sigf(g1.x) * tanh_fast(g2.x));
                float hn = sigf(g2.y) * tanh_fast(cn);
                cB = aB ? cn : cB; hB = aB ? hn : hB; hsB = aB ? hn : 0.f;
            }
            {
                float2 g1 = unpack2(ifC), g2 = unpack2(goC);
                float cn = fmaf(sigf(g1.y), cC, sigf(g1.x) * tanh_fast(g2.x));
                float hn = sigf(g2.y) * tanh_fast(cn);
                cC = aC ? cn : cC; hC = aC ? hn : hC; hsC = aC ? hn : 0.f;
            }
            {
                float2 g1 = unpack2(ifD), g2 = unpack2(goD);
                float cn = fmaf(sigf(g1.y), cD, sigf(g1.x) * tanh_fast(g2.x));
                float hn = sigf(g2.y) * tanh_fast(cn);
                cD = aD ? cn : cD; hD = aD ? hn : hD; hsD = aD ? hn : 0.f;
            }
            hbuf[bsel ^ 1][0][lane] = pack2(hA, hB);
            hbuf[bsel ^ 1][1][lane] = pack2(hC, hD);
            hist[(slot * 2 + 0) * 33 + lane] = pack2(hsA, hsB);
            hist[(slot * 2 + 1) * 33 + lane] = pack2(hsC, hsD);
        } else {
            hbuf[bsel ^ 1][0][lane] = pack2(hA, hB);
            hbuf[bsel ^ 1][1][lane] = pack2(hC, hD);
            hist[(slot * 2 + 0) * 33 + lane] = 0ULL;
            hist[(slot * 2 + 1) * 33 + lane] = 0ULL;
        }
        if (pf) {
            xbuf[bsel ^ 1][0][lane] = pack2(xnA, xnB);
            xbuf[bsel ^ 1][1][lane] = pack2(xnC, xnD);
        }
        __syncwarp();

        // bulk head phase: lane = (pair, timestep) over the finished 16-step chunk
        if (slot == CHUNK - 1) {
            const int tt = lane & 15;
            const int pr = lane >> 4;
            const int hb = (tt * 2 + pr) * 33;
            ull p0 = 0ULL, p1 = 0ULL, pl = 0ULL;
            #pragma unroll
            for (int j = 0; j < HIDDEN; ++j) {
                const ull hv = hist[hb + j];
                p0 = fma2(hv, wcd0[j], p0);
                p1 = fma2(hv, wcd1[j], p1);
                pl = fma2(hv, wcdl[j], pl);
            }
            const float2 q0 = unpack2(p0), q1 = unpack2(p1), ql = unpack2(pl);
            const int tg = t - (CHUNK - 1) + tt;
            const int sA = s0 + pr * 2;
            const size_t oA = (size_t)sA * TSTEPS + tg;
            const size_t oB = oA + TSTEPS;
            reinterpret_cast<float2*>(pos_out)[oA] = make_float2(q0.x + cb0, q1.x + cb1);
            reinterpret_cast<float2*>(pos_out)[oB] = make_float2(q0.y + cb0, q1.y + cb1);
            lv_out[oA] = sigf(ql.x + blv);
            lv_out[oB] = sigf(ql.y + blv);
            __syncwarp();
        }
    }

    hT_out[(s0 + 0) * HIDDEN + lane] = hA;
    hT_out[(s0 + 1) * HIDDEN + lane] = hB;
    hT_out[(s0 + 2) * HIDDEN + lane] = hC;
    hT_out[(s0 + 3) * HIDDEN + lane] = hD;
    cT_out[(s0 + 0) * HIDDEN + lane] = cA;
    cT_out[(s0 + 1) * HIDDEN + lane] = cB;
    cT_out[(s0 + 2) * HIDDEN + lane] = cC;
    cT_out[(s0 + 3) * HIDDEN + lane] = cD;
}

extern "C" void kernel_launch(void* const* d_in, const int* in_sizes, int n_in,
                              void* d_out, int out_size)
{
    const float* x    = (const float*)d_in[0];
    const float* h0   = (const float*)d_in[1];
    const float* c0   = (const float*)d_in[2];
    const float* W_ih = (const float*)d_in[3];
    const float* W_hh = (const float*)d_in[4];
    const float* b_ih = (const float*)d_in[5];
    const float* b_hh = (const float*)d_in[6];
    const float* W_all= (const float*)d_in[7];
    const float* b_all= (const float*)d_in[8];
    const float* W_pos= (const float*)d_in[9];
    const float* b_pos= (const float*)d_in[10];
    const float* W_lv = (const float*)d_in[11];
    const float* b_lv = (const float*)d_in[12];
    float* out = (float*)d_out;

    dim3 grid(BATCH / 4);     // 1024 one-warp blocks -> near-perfect SM balance
    dim3 block(32);
    lstm_fused_kernel<<<grid, block>>>(x, h0, c0, W_ih, W_hh, b_ih, b_hh,
                                       W_all, b_all, W_pos, b_pos, W_lv, b_lv, out);
}